// round 8
// baseline (speedup 1.0000x reference)
#include <cuda_runtime.h>
#include <math.h>

#define NTHREADS 512
#define COUNT_SHIFT 52
#define SUM_MASK ((1ULL << COUNT_SHIFT) - 1ULL)
#define FP_SCALE 1073741824.0f  /* 2^30 */

// Packed accumulator: bits[52:64) = arrival count, bits[0:52) = fixed-point sum.
__device__ unsigned long long g_acc = 0ULL;

__device__ __forceinline__ float2 ldg_nc2(const float* p) {
    float2 v;
    asm volatile("ld.global.nc.v2.f32 {%0,%1}, [%2];"
                 : "=f"(v.x), "=f"(v.y) : "l"(p));
    return v;
}

__global__ void __launch_bounds__(NTHREADS)
smpl_fused_kernel(const float* __restrict__ corr,
                  const float* __restrict__ gt,
                  const float* __restrict__ vis,
                  float* __restrict__ out,
                  int total, int hw_shift, int h, int w, double final_scale) {
    const int hw = 1 << hw_shift;
    float acc = 0.0f;

    const int t = blockIdx.x * NTHREADS + threadIdx.x;
    if (t < total) {
        const int b = t >> hw_shift;
        const int p = t & (hw - 1);

        const float g0 = __ldg(gt + (size_t)b * 2 * hw + p);       // channel 0 -> x
        const float g1 = __ldg(gt + (size_t)b * 2 * hw + hw + p);  // channel 1 -> y
        const float v  = __ldg(vis + (size_t)b * hw + p);

        const float gx = (g0 + 1.0f) * (float)(w - 1) * 0.5f;
        const float gy = (g1 + 1.0f) * (float)(h - 1) * 0.5f;
        const float fx = floorf(gx);
        const float fy = floorf(gy);

        const float wy0 = fy + 1.0f - gy;
        const float wy1 = gy - fy;
        const float wx0 = fx + 1.0f - gx;
        const float wx1 = gx - fx;

        const float wt0 = wy0 * wx0;
        const float wt1 = wy0 * wx1;
        const float wt2 = wy1 * wx0;
        const float wt3 = wy1 * wx1;

        // clamped row/col indices (clip in float then cast, matching reference)
        const float x0f = fminf(fmaxf(fy,        0.0f), (float)(h - 1));
        const float x1f = fminf(fmaxf(fy + 1.0f, 0.0f), (float)(h - 1));
        const float y0f = fminf(fmaxf(fx,        0.0f), (float)(w - 1));
        const float y1f = fminf(fmaxf(fx + 1.0f, 0.0f), (float)(w - 1));
        const int x0 = (int)x0f, x1 = (int)x1f;
        const int y0 = (int)y0f, y1 = (int)y1f;

        const float* __restrict__ base0 = corr + ((size_t)b * hw + p) * hw + x0 * w;
        const float* __restrict__ base1 = corr + ((size_t)b * hw + p) * hw + x1 * w;

        // Branchless gather: aligned LDG.64 pairs + predicated selects.
        const int y0a = y0 & ~1, y1a = y1 & ~1;
        const bool y0odd = (y0 & 1), y1odd = (y1 & 1);
        const float2 p00 = ldg_nc2(base0 + y0a);
        const float2 p01 = ldg_nc2(base0 + y1a);
        const float2 p10 = ldg_nc2(base1 + y0a);
        const float2 p11 = ldg_nc2(base1 + y1a);
        const float c0 = y0odd ? p00.y : p00.x;
        const float c1 = y1odd ? p01.y : p01.x;
        const float c2 = y0odd ? p10.y : p10.x;
        const float c3 = y1odd ? p11.y : p11.x;

        acc += fabsf(c0 * v - wt0 * v);
        acc += fabsf(c1 * v - wt1 * v);
        acc += fabsf(c2 * v - wt2 * v);
        acc += fabsf(c3 * v - wt3 * v);
    }

    // Block reduction: warp shuffles -> shared -> warp 0.
    __shared__ float smem[NTHREADS / 32];
    const int lane = threadIdx.x & 31;
    const int wid  = threadIdx.x >> 5;
    #pragma unroll
    for (int off = 16; off > 0; off >>= 1)
        acc += __shfl_down_sync(0xFFFFFFFFu, acc, off);
    if (lane == 0) smem[wid] = acc;
    __syncthreads();
    if (wid == 0) {
        float s = (lane < (NTHREADS >> 5)) ? smem[lane] : 0.0f;
        #pragma unroll
        for (int off = 16; off > 0; off >>= 1)
            s += __shfl_down_sync(0xFFFFFFFFu, s, off);
        if (lane == 0) {
            // One packed atomic: count in high bits, fixed-point sum in low bits.
            const unsigned long long q =
                (unsigned long long)__float2ull_rn(s * FP_SCALE);
            const unsigned long long pack = (1ULL << COUNT_SHIFT) | q;
            const unsigned long long old = atomicAdd(&g_acc, pack);
            const unsigned int cnt = (unsigned int)(old >> COUNT_SHIFT);
            if (cnt == gridDim.x - 1) {
                const unsigned long long tot = (old & SUM_MASK) + q;
                out[0] = (float)((double)tot * final_scale);
                atomicExch(&g_acc, 0ULL);  // reset for next graph replay
            }
        }
    }
}

extern "C" void kernel_launch(void* const* d_in, const int* in_sizes, int n_in,
                              void* d_out, int out_size) {
    const float* corr = (const float*)d_in[0];  // [B, h*w, h*w]
    const float* gt   = (const float*)d_in[1];  // [B, 2, h, w]
    const float* vis  = (const float*)d_in[2];  // [B, 1, h, w]
    float* out = (float*)d_out;

    const long long n_corr = in_sizes[0];
    const long long n_vis  = in_sizes[2];
    const int hw = (int)(n_corr / n_vis);
    const int B  = (int)(n_vis / hw);
    int h = 1;
    while (h * h < hw) h++;
    const int w = h;

    int hw_shift = 0;
    while ((1 << hw_shift) < hw) hw_shift++;

    const int total = B * hw;
    const double final_scale =
        (1.0 / (double)FP_SCALE) * (1.0 / (4.0 * (double)total));

    const int grid = (total + NTHREADS - 1) / NTHREADS;  // 128 for B=16, hw=4096
    smpl_fused_kernel<<<grid, NTHREADS>>>(corr, gt, vis, out,
                                          total, hw_shift, h, w, final_scale);
}

// round 9
// speedup vs baseline: 1.3413x; 1.3413x over previous
#include <cuda_runtime.h>
#include <math.h>

#define NTHREADS 512
#define COUNT_SHIFT 52
#define SUM_MASK ((1ULL << COUNT_SHIFT) - 1ULL)
#define FP_SCALE 1073741824.0f  /* 2^30 */

// Packed accumulator: bits[52:64) = arrival count, bits[0:52) = fixed-point sum.
__device__ unsigned long long g_acc = 0ULL;

__device__ __forceinline__ float2 ldg_nc2(const float* p) {
    float2 v;
    asm volatile("ld.global.nc.v2.f32 {%0,%1}, [%2];"
                 : "=f"(v.x), "=f"(v.y) : "l"(p));
    return v;
}

__global__ void __launch_bounds__(NTHREADS)
smpl_fused_kernel(const float* __restrict__ corr,
                  const float* __restrict__ gt,
                  const float* __restrict__ vis,
                  float* __restrict__ out,
                  int total, int hw_shift, int h, int w, double final_scale) {
    const int hw = 1 << hw_shift;
    float acc = 0.0f;

    const int t = blockIdx.x * NTHREADS + threadIdx.x;
    if (t < total) {
        const int b = t >> hw_shift;
        const int p = t & (hw - 1);

        const float g0 = __ldg(gt + (size_t)b * 2 * hw + p);       // channel 0 -> x
        const float g1 = __ldg(gt + (size_t)b * 2 * hw + hw + p);  // channel 1 -> y
        const float v  = __ldg(vis + (size_t)b * hw + p);

        const float gx = (g0 + 1.0f) * (float)(w - 1) * 0.5f;
        const float gy = (g1 + 1.0f) * (float)(h - 1) * 0.5f;
        const float fx = floorf(gx);
        const float fy = floorf(gy);

        const float wy0 = fy + 1.0f - gy;
        const float wy1 = gy - fy;
        const float wx0 = fx + 1.0f - gx;
        const float wx1 = gx - fx;

        const float wt0 = wy0 * wx0;
        const float wt1 = wy0 * wx1;
        const float wt2 = wy1 * wx0;
        const float wt3 = wy1 * wx1;

        // clamped row/col indices (clip in float then cast, matching reference)
        const float x0f = fminf(fmaxf(fy,        0.0f), (float)(h - 1));
        const float x1f = fminf(fmaxf(fy + 1.0f, 0.0f), (float)(h - 1));
        const float y0f = fminf(fmaxf(fx,        0.0f), (float)(w - 1));
        const float y1f = fminf(fmaxf(fx + 1.0f, 0.0f), (float)(w - 1));
        const int x0 = (int)x0f, x1 = (int)x1f;
        const int y0 = (int)y0f, y1 = (int)y1f;

        const float* __restrict__ base0 = corr + ((size_t)b * hw + p) * hw + x0 * w;
        const float* __restrict__ base1 = corr + ((size_t)b * hw + p) * hw + x1 * w;

        float c0, c1, c2, c3;
        // Fast path: adjacent columns, 8B-aligned -> 2x LDG.64 (one wavefront each).
        if ((y1 == y0 + 1) && ((y0 & 1) == 0)) {
            const float2 a  = ldg_nc2(base0 + y0);
            const float2 bb = ldg_nc2(base1 + y0);
            c0 = a.x; c1 = a.y; c2 = bb.x; c3 = bb.y;
        } else {
            c0 = __ldg(base0 + y0);
            c1 = __ldg(base0 + y1);
            c2 = __ldg(base1 + y0);
            c3 = __ldg(base1 + y1);
        }

        acc += fabsf(c0 * v - wt0 * v);
        acc += fabsf(c1 * v - wt1 * v);
        acc += fabsf(c2 * v - wt2 * v);
        acc += fabsf(c3 * v - wt3 * v);
    }

    // Block reduction: warp shuffles -> shared -> warp 0.
    __shared__ float smem[NTHREADS / 32];
    const int lane = threadIdx.x & 31;
    const int wid  = threadIdx.x >> 5;
    #pragma unroll
    for (int off = 16; off > 0; off >>= 1)
        acc += __shfl_down_sync(0xFFFFFFFFu, acc, off);
    if (lane == 0) smem[wid] = acc;
    __syncthreads();
    if (wid == 0) {
        float s = (lane < (NTHREADS >> 5)) ? smem[lane] : 0.0f;
        #pragma unroll
        for (int off = 16; off > 0; off >>= 1)
            s += __shfl_down_sync(0xFFFFFFFFu, s, off);
        if (lane == 0) {
            // One packed atomic: count in high bits, fixed-point sum in low bits.
            const unsigned long long q =
                (unsigned long long)__float2ull_rn(s * FP_SCALE);
            const unsigned long long pack = (1ULL << COUNT_SHIFT) | q;
            const unsigned long long old = atomicAdd(&g_acc, pack);
            const unsigned int cnt = (unsigned int)(old >> COUNT_SHIFT);
            if (cnt == gridDim.x - 1) {
                const unsigned long long tot = (old & SUM_MASK) + q;
                out[0] = (float)((double)tot * final_scale);
                atomicExch(&g_acc, 0ULL);  // reset for next graph replay
            }
        }
    }
}

extern "C" void kernel_launch(void* const* d_in, const int* in_sizes, int n_in,
                              void* d_out, int out_size) {
    const float* corr = (const float*)d_in[0];  // [B, h*w, h*w]
    const float* gt   = (const float*)d_in[1];  // [B, 2, h, w]
    const float* vis  = (const float*)d_in[2];  // [B, 1, h, w]
    float* out = (float*)d_out;

    const long long n_corr = in_sizes[0];
    const long long n_vis  = in_sizes[2];
    const int hw = (int)(n_corr / n_vis);
    const int B  = (int)(n_vis / hw);
    int h = 1;
    while (h * h < hw) h++;
    const int w = h;

    int hw_shift = 0;
    while ((1 << hw_shift) < hw) hw_shift++;

    const int total = B * hw;
    const double final_scale =
        (1.0 / (double)FP_SCALE) * (1.0 / (4.0 * (double)total));

    const int grid = (total + NTHREADS - 1) / NTHREADS;  // 128 for B=16, hw=4096
    smpl_fused_kernel<<<grid, NTHREADS>>>(corr, gt, vis, out,
                                          total, hw_shift, h, w, final_scale);
}

// round 10
// speedup vs baseline: 1.3478x; 1.0048x over previous
#include <cuda_runtime.h>
#include <math.h>

#define NTHREADS 512
#define COUNT_SHIFT 52
#define SUM_MASK ((1ULL << COUNT_SHIFT) - 1ULL)
#define FP_SCALE 1073741824.0f  /* 2^30 */

// Packed accumulator: bits[52:64) = arrival count, bits[0:52) = fixed-point sum.
__device__ unsigned long long g_acc = 0ULL;

__device__ __forceinline__ float2 ldg_nc2(const float* p) {
    float2 v;
    asm volatile("ld.global.nc.v2.f32 {%0,%1}, [%2];"
                 : "=f"(v.x), "=f"(v.y) : "l"(p));
    return v;
}

__global__ void __launch_bounds__(NTHREADS)
smpl_fused_kernel(const float* __restrict__ corr,
                  const float* __restrict__ gt,
                  const float* __restrict__ vis,
                  float* __restrict__ out,
                  int total, int items_per_block, int hw_shift,
                  int h, int w, double final_scale) {
    const int hw = 1 << hw_shift;
    float acc = 0.0f;

    const int t = blockIdx.x * items_per_block + threadIdx.x;
    if ((int)threadIdx.x < items_per_block && t < total) {
        const int b = t >> hw_shift;
        const int p = t & (hw - 1);

        const float g0 = __ldg(gt + (size_t)b * 2 * hw + p);       // channel 0 -> x
        const float g1 = __ldg(gt + (size_t)b * 2 * hw + hw + p);  // channel 1 -> y
        const float v  = __ldg(vis + (size_t)b * hw + p);

        const float gx = (g0 + 1.0f) * (float)(w - 1) * 0.5f;
        const float gy = (g1 + 1.0f) * (float)(h - 1) * 0.5f;
        const float fx = floorf(gx);
        const float fy = floorf(gy);

        const float wy0 = fy + 1.0f - gy;
        const float wy1 = gy - fy;
        const float wx0 = fx + 1.0f - gx;
        const float wx1 = gx - fx;

        const float wt0 = wy0 * wx0;
        const float wt1 = wy0 * wx1;
        const float wt2 = wy1 * wx0;
        const float wt3 = wy1 * wx1;

        // clamped row/col indices (clip in float then cast, matching reference)
        const float x0f = fminf(fmaxf(fy,        0.0f), (float)(h - 1));
        const float x1f = fminf(fmaxf(fy + 1.0f, 0.0f), (float)(h - 1));
        const float y0f = fminf(fmaxf(fx,        0.0f), (float)(w - 1));
        const float y1f = fminf(fmaxf(fx + 1.0f, 0.0f), (float)(w - 1));
        const int x0 = (int)x0f, x1 = (int)x1f;
        const int y0 = (int)y0f, y1 = (int)y1f;

        const float* __restrict__ base0 = corr + ((size_t)b * hw + p) * hw + x0 * w;
        const float* __restrict__ base1 = corr + ((size_t)b * hw + p) * hw + x1 * w;

        float c0, c1, c2, c3;
        // Fast path: adjacent columns, 8B-aligned -> 2x LDG.64 (one wavefront each).
        if ((y1 == y0 + 1) && ((y0 & 1) == 0)) {
            const float2 a  = ldg_nc2(base0 + y0);
            const float2 bb = ldg_nc2(base1 + y0);
            c0 = a.x; c1 = a.y; c2 = bb.x; c3 = bb.y;
        } else {
            c0 = __ldg(base0 + y0);
            c1 = __ldg(base0 + y1);
            c2 = __ldg(base1 + y0);
            c3 = __ldg(base1 + y1);
        }

        // |c*v - wt*v| = v * |c - wt|  (vis mask is non-negative)
        const float s01 = fabsf(c0 - wt0) + fabsf(c1 - wt1);
        const float s23 = fabsf(c2 - wt2) + fabsf(c3 - wt3);
        acc = v * (s01 + s23);
    }

    // Block reduction: warp shuffles -> shared -> warp 0.
    __shared__ float smem[NTHREADS / 32];
    const int lane = threadIdx.x & 31;
    const int wid  = threadIdx.x >> 5;
    #pragma unroll
    for (int off = 16; off > 0; off >>= 1)
        acc += __shfl_down_sync(0xFFFFFFFFu, acc, off);
    if (lane == 0) smem[wid] = acc;
    __syncthreads();
    if (wid == 0) {
        float s = (lane < (NTHREADS >> 5)) ? smem[lane] : 0.0f;
        #pragma unroll
        for (int off = 16; off > 0; off >>= 1)
            s += __shfl_down_sync(0xFFFFFFFFu, s, off);
        if (lane == 0) {
            // One packed atomic: count in high bits, fixed-point sum in low bits.
            const unsigned long long q =
                (unsigned long long)__float2ull_rn(s * FP_SCALE);
            const unsigned long long pack = (1ULL << COUNT_SHIFT) | q;
            const unsigned long long old = atomicAdd(&g_acc, pack);
            const unsigned int cnt = (unsigned int)(old >> COUNT_SHIFT);
            if (cnt == gridDim.x - 1) {
                const unsigned long long tot = (old & SUM_MASK) + q;
                out[0] = (float)((double)tot * final_scale);
                atomicExch(&g_acc, 0ULL);  // reset for next graph replay
            }
        }
    }
}

extern "C" void kernel_launch(void* const* d_in, const int* in_sizes, int n_in,
                              void* d_out, int out_size) {
    const float* corr = (const float*)d_in[0];  // [B, h*w, h*w]
    const float* gt   = (const float*)d_in[1];  // [B, 2, h, w]
    const float* vis  = (const float*)d_in[2];  // [B, 1, h, w]
    float* out = (float*)d_out;

    const long long n_corr = in_sizes[0];
    const long long n_vis  = in_sizes[2];
    const int hw = (int)(n_corr / n_vis);
    const int B  = (int)(n_vis / hw);
    int h = 1;
    while (h * h < hw) h++;
    const int w = h;

    int hw_shift = 0;
    while ((1 << hw_shift) < hw) hw_shift++;

    const int total = B * hw;
    const double final_scale =
        (1.0 / (double)FP_SCALE) * (1.0 / (4.0 * (double)total));

    // Spread across all 148 SMs: one CTA per SM, block-contiguous item ranges.
    int grid = 148;
    int items = (total + grid - 1) / grid;          // 443 for 65536
    if (items > NTHREADS) {                         // safety for other shapes
        grid = (total + NTHREADS - 1) / NTHREADS;
        items = NTHREADS;
    }

    smpl_fused_kernel<<<grid, NTHREADS>>>(corr, gt, vis, out,
                                          total, items, hw_shift, h, w,
                                          final_scale);
}